// round 11
// baseline (speedup 1.0000x reference)
#include <cuda_runtime.h>
#include <cstdint>

#define HH 512
#define WW 512
#define HWSZ (HH * WW)
#define RSTRIP 4
#define MAXBLK 2048

__device__ float g_part[6 * MAXBLK];
__device__ unsigned g_cnt;   // zero-init; last block resets each launch

// ---- packed f32x2 helpers (Blackwell FFMA2 path) ----
#define MUL2(out, a, b)    asm("mul.rn.f32x2 %0, %1, %2;"     : "=l"(out) : "l"(a), "l"(b))
#define ADD2(out, a, b)    asm("add.rn.f32x2 %0, %1, %2;"     : "=l"(out) : "l"(a), "l"(b))
#define FMA2(out, a, b, c) asm("fma.rn.f32x2 %0, %1, %2, %3;" : "=l"(out) : "l"(a), "l"(b), "l"(c))
#define PACK2(out, lo, hi) asm("mov.b64 %0, {%1, %2};" : "=l"(out) : "f"(lo), "f"(hi))
#define UNPK2(lo, hi, in)  asm("mov.b64 {%0, %1}, %2;" : "=f"(lo), "=f"(hi) : "l"(in))

__device__ __forceinline__ float tanh_approx(float x) {
    float r; asm("tanh.approx.f32 %0, %1;" : "=f"(r) : "f"(x)); return r;
}
__device__ __forceinline__ float lg2_approx(float x) {
    float r; asm("lg2.approx.f32 %0, %1;" : "=f"(r) : "f"(x)); return r;
}

// gather t-bit (1.0f vs 0.0f) of 8 target words into bits 0..7
__device__ __forceinline__ unsigned pack8(uint4 c0, uint4 c1) {
    unsigned a = __byte_perm(__byte_perm(c0.x, c0.y, 0x0073),
                             __byte_perm(c0.z, c0.w, 0x0073), 0x5410);
    unsigned b = __byte_perm(__byte_perm(c1.x, c1.y, 0x0073),
                             __byte_perm(c1.z, c1.w, 0x0073), 0x5410);
    unsigned ba = ((a & 0x01010101u) * 0x01020408u) >> 24;
    unsigned bb = ((b & 0x01010101u) * 0x01020408u) >> 24;
    return ba | (bb << 4);
}

// 20-bit window for row gy, cols x0-2 .. x0+17 (bit k <-> col x0-2+k). OOB bits 0.
__device__ __forceinline__ unsigned win_load16(const float* __restrict__ tb, int gy, int x0) {
    unsigned w = 0u;
    if ((unsigned)gy < (unsigned)HH) {
        const float* row = tb + gy * WW + x0;
        uint4 c0 = *reinterpret_cast<const uint4*>(row);
        uint4 c1 = *reinterpret_cast<const uint4*>(row + 4);
        uint4 c2 = *reinterpret_cast<const uint4*>(row + 8);
        uint4 c3 = *reinterpret_cast<const uint4*>(row + 12);
        w = (pack8(c0, c1) << 2) | (pack8(c2, c3) << 10);
        if (x0 > 0) {
            uint2 l = *reinterpret_cast<const uint2*>(row - 2);
            w |= ((l.x >> 29) & 1u) | (((l.y >> 29) & 1u) << 1);
        }
        if (x0 + 16 < WW) {
            uint2 r = *reinterpret_cast<const uint2*>(row + 16);
            w |= (((r.x >> 29) & 1u) << 18) | (((r.y >> 29) & 1u) << 19);
        }
    }
    return w;
}

__device__ __forceinline__ unsigned or5(unsigned x)  { unsigned y = x | (x >> 1); unsigned z = y | (y >> 2); return z | (x >> 4); }
__device__ __forceinline__ unsigned or3(unsigned x)  { return x | (x >> 1) | (x >> 2); }
__device__ __forceinline__ unsigned and5(unsigned x) { unsigned y = x & (x >> 1); unsigned z = y & (y >> 2); return z & (x >> 4); }
__device__ __forceinline__ unsigned and3(unsigned x) { return x & (x >> 1) & (x >> 2); }

__global__ void __launch_bounds__(256) combined_loss_kernel(
    const float* __restrict__ inp,
    const float* __restrict__ tgt,
    float* __restrict__ out,
    float invN)
{
    const int b   = blockIdx.x;
    const int img = b >> 4;                     // 16 blocks/image, 32 rows each
    const int blk = b & 15;
    const int tid = threadIdx.x;
    const int y0  = (blk << 5) | ((tid >> 5) << 2);   // 8 row-strips of 4 rows
    const int x0  = (tid & 31) << 4;                  // 16-px column group

    const float* tb = tgt + (size_t)img * HWSZ;
    const float* ib = inp + (size_t)img * HWSZ + x0;

    unsigned wm2 = win_load16(tb, y0 - 2, x0);
    unsigned wm1 = win_load16(tb, y0 - 1, x0);
    unsigned w0  = win_load16(tb, y0,     x0);
    unsigned wp1 = win_load16(tb, y0 + 1, x0);

    uint64_t HALF2;
    PACK2(HALF2, 0.5f, 0.5f);
    const uint64_t SFLIP = 0x8000000080000000ull;

    uint64_t aU2 = 0, aW2 = 0, aF2 = 0, aB2 = 0, aY2 = 0;   // packed (0.0f,0.0f)
    int aT = 0;

    #pragma unroll
    for (int r = 0; r < RSTRIP; r++) {
        const int gy = y0 + r;
        const unsigned wp2 = win_load16(tb, gy + 2, x0);
        const float* irow = ib + gy * WW;
        const ulonglong2 qa = *reinterpret_cast<const ulonglong2*>(irow);
        const ulonglong2 qb = *reinterpret_cast<const ulonglong2*>(irow + 4);
        const ulonglong2 qc = *reinterpret_cast<const ulonglong2*>(irow + 8);
        const ulonglong2 qd = *reinterpret_cast<const ulonglong2*>(irow + 12);
        const uint64_t xp[8] = { qa.x, qa.y, qb.x, qb.y, qc.x, qc.y, qd.x, qd.y };

        // bit-parallel morphology: bit j valid for pixels j=0..15
        const unsigned anyb = or5(w0) | (or3(wm1) >> 1) | (or3(wp1) >> 1) | (wm2 >> 2) | (wp2 >> 2);
        const unsigned allb = and5(w0) & (and3(wm1) >> 1) & (and3(wp1) >> 1) & (wm2 >> 2) & (wp2 >> 2);
        const unsigned bnd   = anyb & ~allb;
        const unsigned tbits = (w0 >> 2) & 0xFFFFu;

        aT += __popc(tbits);
        const unsigned nt = ~tbits;
        const unsigned nb = ~bnd;

        #pragma unroll
        for (int k = 0; k < 8; k++) {
            const int j = 2 * k;
            // +-0.5 sign pairs from mask bits j, j+1
            const unsigned s0 = ((nt << (31 - j)) & 0x80000000u) | 0x3F000000u;
            const unsigned s1 = ((nt << (30 - j)) & 0x80000000u) | 0x3F000000u;
            const unsigned b0 = ((nb << (31 - j)) & 0x80000000u) | 0x3F000000u;
            const unsigned b1 = ((nb << (30 - j)) & 0x80000000u) | 0x3F000000u;
            uint64_t sgt2, sgb2;
            PACK2(sgt2, __uint_as_float(s0), __uint_as_float(s1));
            PACK2(sgb2, __uint_as_float(b0), __uint_as_float(b1));

            uint64_t harg; MUL2(harg, xp[k], HALF2);
            float h0, h1; UNPK2(h0, h1, harg);
            uint64_t th2; PACK2(th2, tanh_approx(h0), tanh_approx(h1));

            uint64_t pt2; FMA2(pt2, sgt2, th2, HALF2);        // prob of true class
            float p0, p1; UNPK2(p0, p1, pt2);
            uint64_t lp2; PACK2(lp2, lg2_approx(p0), lg2_approx(p1));  // bce = -ln2*lp

            uint64_t ompt2; FMA2(ompt2, sgt2 ^ SFLIP, th2, HALF2);     // 1 - pt
            ADD2(aU2, aU2, pt2);
            FMA2(aW2, sgt2, pt2, aW2);
            uint64_t osq; MUL2(osq, ompt2, ompt2);
            FMA2(aF2, osq, lp2, aF2);
            ADD2(aB2, aB2, lp2);
            FMA2(aY2, sgb2, lp2, aY2);
        }

        wm2 = wm1; wm1 = w0; w0 = wp1; wp1 = wp2;
    }

    // horizontal fold of packed accumulators
    float u0,u1,w0f,w1f,f0,f1,bb0,bb1,yy0,yy1;
    UNPK2(u0,u1,aU2); UNPK2(w0f,w1f,aW2); UNPK2(f0,f1,aF2);
    UNPK2(bb0,bb1,aB2); UNPK2(yy0,yy1,aY2);

    float v[6] = { f0+f1, w0f+w1f, u0+u1, (float)aT, bb0+bb1, yy0+yy1 };
    #pragma unroll
    for (int q = 0; q < 6; q++) {
        #pragma unroll
        for (int off = 16; off > 0; off >>= 1)
            v[q] += __shfl_down_sync(0xFFFFFFFFu, v[q], off);
    }

    __shared__ float sred[8][6];
    const int wid  = tid >> 5;
    const int lane = tid & 31;
    if (lane == 0) {
        #pragma unroll
        for (int q = 0; q < 6; q++) sred[wid][q] = v[q];
    }
    __syncthreads();

    __shared__ bool isLast;
    if (tid == 0) {
        #pragma unroll
        for (int q = 0; q < 6; q++) {
            float acc = sred[0][q];
            #pragma unroll
            for (int w = 1; w < 8; w++) acc += sred[w][q];
            g_part[q * MAXBLK + b] = acc;
        }
        __threadfence();
        isLast = (atomicAdd(&g_cnt, 1u) == gridDim.x - 1);
    }
    __syncthreads();

    if (isLast) {
        __threadfence();
        const int nb2 = gridDim.x;
        double d[6] = { 0, 0, 0, 0, 0, 0 };
        for (int i = tid; i < nb2; i += 256) {
            #pragma unroll
            for (int q = 0; q < 6; q++) d[q] += (double)g_part[q * MAXBLK + i];
        }
        #pragma unroll
        for (int q = 0; q < 6; q++) {
            #pragma unroll
            for (int off = 16; off > 0; off >>= 1)
                d[q] += __shfl_down_sync(0xFFFFFFFFu, d[q], off);
        }
        __shared__ double dred[8][6];
        if (lane == 0) {
            #pragma unroll
            for (int q = 0; q < 6; q++) dred[wid][q] = d[q];
        }
        __syncthreads();
        if (tid == 0) {
            double t[6];
            #pragma unroll
            for (int q = 0; q < 6; q++) {
                double acc = dred[0][q];
                #pragma unroll
                for (int w = 1; w < 8; w++) acc += dred[w][q];
                t[q] = acc;
            }
            const double LN2 = 0.693147180559945309;
            const double N  = 1.0 / (double)invN;
            const double T  = t[3];
            const double V  = t[1] + 0.5 * t[2];        // sum(p*t)
            const double sumP = 2.0 * t[1] + (N - T);   // sum(p)
            const double focal = 0.25 * (-LN2 * t[0]) / N;
            const double dice  = (2.0 * V + 1e-6) / (sumP + T + 1e-6);
            const double bl    = (-LN2) * (3.5 * t[4] + 5.0 * t[5]) / N;
            out[0] = (float)(0.3 * focal + 0.4 * (1.0 - dice) + 0.3 * bl);
            g_cnt = 0;
        }
    }
}

extern "C" void kernel_launch(void* const* d_in, const int* in_sizes, int n_in,
                              void* d_out, int out_size) {
    const float* inp = (const float*)d_in[0];
    const float* tgt = (const float*)d_in[1];
    const int N = in_sizes[0];
    const int nimg = N / HWSZ;
    const int nblocks = nimg * 16;   // 16 blocks (32 rows) per image

    combined_loss_kernel<<<nblocks, 256>>>(inp, tgt, (float*)d_out, 1.0f / (float)N);
}

// round 12
// speedup vs baseline: 1.1941x; 1.1941x over previous
#include <cuda_runtime.h>
#include <cstdint>

#define HH 512
#define WW 512
#define HWSZ (HH * WW)
#define RSTRIP 8
#define MAXBLK 2048

__device__ float g_part[6 * MAXBLK];
__device__ unsigned g_cnt;   // zero-init; last block resets each launch

// ---- packed f32x2 helpers (Blackwell FFMA2 path) ----
#define MUL2(out, a, b)    asm("mul.rn.f32x2 %0, %1, %2;"     : "=l"(out) : "l"(a), "l"(b))
#define ADD2(out, a, b)    asm("add.rn.f32x2 %0, %1, %2;"     : "=l"(out) : "l"(a), "l"(b))
#define FMA2(out, a, b, c) asm("fma.rn.f32x2 %0, %1, %2, %3;" : "=l"(out) : "l"(a), "l"(b), "l"(c))
#define PACK2(out, lo, hi) asm("mov.b64 %0, {%1, %2};" : "=l"(out) : "f"(lo), "f"(hi))
#define UNPK2(lo, hi, in)  asm("mov.b64 {%0, %1}, %2;" : "=f"(lo), "=f"(hi) : "l"(in))

__device__ __forceinline__ float tanh_approx(float x) {
    float r; asm("tanh.approx.f32 %0, %1;" : "=f"(r) : "f"(x)); return r;
}
__device__ __forceinline__ float lg2_approx(float x) {
    float r; asm("lg2.approx.f32 %0, %1;" : "=f"(r) : "f"(x)); return r;
}

// gather t-bit (1.0f vs 0.0f) of 8 target words into bits 0..7
__device__ __forceinline__ unsigned pack8(uint4 c0, uint4 c1) {
    unsigned a = __byte_perm(__byte_perm(c0.x, c0.y, 0x0073),
                             __byte_perm(c0.z, c0.w, 0x0073), 0x5410);
    unsigned b = __byte_perm(__byte_perm(c1.x, c1.y, 0x0073),
                             __byte_perm(c1.z, c1.w, 0x0073), 0x5410);
    unsigned ba = ((a & 0x01010101u) * 0x01020408u) >> 24;
    unsigned bb = ((b & 0x01010101u) * 0x01020408u) >> 24;
    return ba | (bb << 4);
}

// 20-bit window for row gy, cols x0-2 .. x0+17 (bit k <-> col x0-2+k). OOB bits 0.
__device__ __forceinline__ unsigned win_load16(const float* __restrict__ tb, int gy, int x0) {
    unsigned w = 0u;
    if ((unsigned)gy < (unsigned)HH) {
        const float* row = tb + gy * WW + x0;
        uint4 c0 = *reinterpret_cast<const uint4*>(row);
        uint4 c1 = *reinterpret_cast<const uint4*>(row + 4);
        uint4 c2 = *reinterpret_cast<const uint4*>(row + 8);
        uint4 c3 = *reinterpret_cast<const uint4*>(row + 12);
        w = (pack8(c0, c1) << 2) | (pack8(c2, c3) << 10);
        if (x0 > 0) {
            uint2 l = *reinterpret_cast<const uint2*>(row - 2);
            w |= ((l.x >> 29) & 1u) | (((l.y >> 29) & 1u) << 1);
        }
        if (x0 + 16 < WW) {
            uint2 r = *reinterpret_cast<const uint2*>(row + 16);
            w |= (((r.x >> 29) & 1u) << 18) | (((r.y >> 29) & 1u) << 19);
        }
    }
    return w;
}

__device__ __forceinline__ unsigned or5(unsigned x)  { unsigned y = x | (x >> 1); unsigned z = y | (y >> 2); return z | (x >> 4); }
__device__ __forceinline__ unsigned or3(unsigned x)  { return x | (x >> 1) | (x >> 2); }
__device__ __forceinline__ unsigned and5(unsigned x) { unsigned y = x & (x >> 1); unsigned z = y & (y >> 2); return z & (x >> 4); }
__device__ __forceinline__ unsigned and3(unsigned x) { return x & (x >> 1) & (x >> 2); }

struct Acc {
    uint64_t U2, W2, F2, B2, Y2;
};

// process one packed pixel pair (px j, j+1 of the 16-px group)
__device__ __forceinline__ void do_pair(
    Acc& a, uint64_t xpair, unsigned nt, unsigned nb, int j,
    uint64_t HALF2, uint64_t SFLIP)
{
    const unsigned s0 = ((nt << (31 - j)) & 0x80000000u) | 0x3F000000u;
    const unsigned s1 = ((nt << (30 - j)) & 0x80000000u) | 0x3F000000u;
    const unsigned b0 = ((nb << (31 - j)) & 0x80000000u) | 0x3F000000u;
    const unsigned b1 = ((nb << (30 - j)) & 0x80000000u) | 0x3F000000u;
    uint64_t sgt2, sgb2;
    PACK2(sgt2, __uint_as_float(s0), __uint_as_float(s1));
    PACK2(sgb2, __uint_as_float(b0), __uint_as_float(b1));

    uint64_t harg; MUL2(harg, xpair, HALF2);
    float h0, h1; UNPK2(h0, h1, harg);
    uint64_t th2; PACK2(th2, tanh_approx(h0), tanh_approx(h1));

    uint64_t pt2; FMA2(pt2, sgt2, th2, HALF2);        // prob of true class
    float p0, p1; UNPK2(p0, p1, pt2);
    uint64_t lp2; PACK2(lp2, lg2_approx(p0), lg2_approx(p1));  // bce = -ln2*lp

    uint64_t ompt2; FMA2(ompt2, sgt2 ^ SFLIP, th2, HALF2);     // 1 - pt
    ADD2(a.U2, a.U2, pt2);
    FMA2(a.W2, sgt2, pt2, a.W2);
    uint64_t osq; MUL2(osq, ompt2, ompt2);
    FMA2(a.F2, osq, lp2, a.F2);
    ADD2(a.B2, a.B2, lp2);
    FMA2(a.Y2, sgb2, lp2, a.Y2);
}

__global__ void __launch_bounds__(256) combined_loss_kernel(
    const float* __restrict__ inp,
    const float* __restrict__ tgt,
    float* __restrict__ out,
    float invN)
{
    const int b    = blockIdx.x;
    const int img  = b >> 3;                    // 8 blocks/image
    const int blk  = b & 7;
    const int tid  = threadIdx.x;
    const int wid  = tid >> 5;
    const int lane = tid & 31;
    const int y0   = ((blk << 3) | wid) * RSTRIP;   // warp strip: 8 rows
    const int x0   = lane << 4;                     // 16-px group; warp = full row

    const float* tb = tgt + (size_t)img * HWSZ;
    const float* ib = inp + (size_t)img * HWSZ + x0;

    unsigned wm2 = win_load16(tb, y0 - 2, x0);
    unsigned wm1 = win_load16(tb, y0 - 1, x0);
    unsigned w0  = win_load16(tb, y0,     x0);
    unsigned wp1 = win_load16(tb, y0 + 1, x0);

    uint64_t HALF2;
    PACK2(HALF2, 0.5f, 0.5f);
    const uint64_t SFLIP = 0x8000000080000000ull;

    Acc a = { 0, 0, 0, 0, 0 };
    int aT = 0;

    #pragma unroll 2
    for (int r = 0; r < RSTRIP; r++) {
        const int gy = y0 + r;
        const unsigned wp2 = win_load16(tb, gy + 2, x0);
        const float* irow = ib + gy * WW;

        // bit-parallel morphology: bit j valid for pixels j=0..15
        const unsigned anyb = or5(w0) | (or3(wm1) >> 1) | (or3(wp1) >> 1) | (wm2 >> 2) | (wp2 >> 2);
        const unsigned allb = and5(w0) & (and3(wm1) >> 1) & (and3(wp1) >> 1) & (wm2 >> 2) & (wp2 >> 2);
        const unsigned bnd   = anyb & ~allb;
        const unsigned tbits = (w0 >> 2) & 0xFFFFu;

        aT += __popc(tbits);
        const unsigned nt = ~tbits;
        const unsigned nb = ~bnd;

        // half A: px 0..7 (only 4 packed inputs live)
        {
            const ulonglong2 qa = *reinterpret_cast<const ulonglong2*>(irow);
            const ulonglong2 qb = *reinterpret_cast<const ulonglong2*>(irow + 4);
            do_pair(a, qa.x, nt, nb, 0, HALF2, SFLIP);
            do_pair(a, qa.y, nt, nb, 2, HALF2, SFLIP);
            do_pair(a, qb.x, nt, nb, 4, HALF2, SFLIP);
            do_pair(a, qb.y, nt, nb, 6, HALF2, SFLIP);
        }
        // half B: px 8..15
        {
            const ulonglong2 qc = *reinterpret_cast<const ulonglong2*>(irow + 8);
            const ulonglong2 qd = *reinterpret_cast<const ulonglong2*>(irow + 12);
            do_pair(a, qc.x, nt, nb, 8,  HALF2, SFLIP);
            do_pair(a, qc.y, nt, nb, 10, HALF2, SFLIP);
            do_pair(a, qd.x, nt, nb, 12, HALF2, SFLIP);
            do_pair(a, qd.y, nt, nb, 14, HALF2, SFLIP);
        }

        wm2 = wm1; wm1 = w0; w0 = wp1; wp1 = wp2;
    }

    // horizontal fold of packed accumulators
    float u0,u1,w0f,w1f,f0,f1,bb0,bb1,yy0,yy1;
    UNPK2(u0,u1,a.U2); UNPK2(w0f,w1f,a.W2); UNPK2(f0,f1,a.F2);
    UNPK2(bb0,bb1,a.B2); UNPK2(yy0,yy1,a.Y2);

    float v[6] = { f0+f1, w0f+w1f, u0+u1, (float)aT, bb0+bb1, yy0+yy1 };
    #pragma unroll
    for (int q = 0; q < 6; q++) {
        #pragma unroll
        for (int off = 16; off > 0; off >>= 1)
            v[q] += __shfl_down_sync(0xFFFFFFFFu, v[q], off);
    }

    __shared__ float sred[8][6];
    if (lane == 0) {
        #pragma unroll
        for (int q = 0; q < 6; q++) sred[wid][q] = v[q];
    }
    __syncthreads();

    __shared__ bool isLast;
    if (tid == 0) {
        #pragma unroll
        for (int q = 0; q < 6; q++) {
            float acc = sred[0][q];
            #pragma unroll
            for (int w = 1; w < 8; w++) acc += sred[w][q];
            g_part[q * MAXBLK + b] = acc;
        }
        __threadfence();
        isLast = (atomicAdd(&g_cnt, 1u) == gridDim.x - 1);
    }
    __syncthreads();

    if (isLast) {
        __threadfence();
        const int nb2 = gridDim.x;
        double d[6] = { 0, 0, 0, 0, 0, 0 };
        for (int i = tid; i < nb2; i += 256) {
            #pragma unroll
            for (int q = 0; q < 6; q++) d[q] += (double)g_part[q * MAXBLK + i];
        }
        #pragma unroll
        for (int q = 0; q < 6; q++) {
            #pragma unroll
            for (int off = 16; off > 0; off >>= 1)
                d[q] += __shfl_down_sync(0xFFFFFFFFu, d[q], off);
        }
        __shared__ double dred[8][6];
        if (lane == 0) {
            #pragma unroll
            for (int q = 0; q < 6; q++) dred[wid][q] = d[q];
        }
        __syncthreads();
        if (tid == 0) {
            double t[6];
            #pragma unroll
            for (int q = 0; q < 6; q++) {
                double acc = dred[0][q];
                #pragma unroll
                for (int w = 1; w < 8; w++) acc += dred[w][q];
                t[q] = acc;
            }
            const double LN2 = 0.693147180559945309;
            const double N  = 1.0 / (double)invN;
            const double T  = t[3];
            const double V  = t[1] + 0.5 * t[2];        // sum(p*t)
            const double sumP = 2.0 * t[1] + (N - T);   // sum(p)
            const double focal = 0.25 * (-LN2 * t[0]) / N;
            const double dice  = (2.0 * V + 1e-6) / (sumP + T + 1e-6);
            const double bl    = (-LN2) * (3.5 * t[4] + 5.0 * t[5]) / N;
            out[0] = (float)(0.3 * focal + 0.4 * (1.0 - dice) + 0.3 * bl);
            g_cnt = 0;
        }
    }
}

extern "C" void kernel_launch(void* const* d_in, const int* in_sizes, int n_in,
                              void* d_out, int out_size) {
    const float* inp = (const float*)d_in[0];
    const float* tgt = (const float*)d_in[1];
    const int N = in_sizes[0];
    const int nimg = N / HWSZ;
    const int nblocks = nimg * 8;   // 8 blocks (64 rows) per image

    combined_loss_kernel<<<nblocks, 256>>>(inp, tgt, (float*)d_out, 1.0f / (float)N);
}

// round 13
// speedup vs baseline: 1.4552x; 1.2186x over previous
#include <cuda_runtime.h>
#include <cstdint>

#define HH 512
#define WW 512
#define HWSZ (HH * WW)
#define RSTRIP 8
#define MAXBLK 2048

__device__ float g_part[5 * MAXBLK];
__device__ unsigned g_cnt;   // zero-init; last block resets each launch

// ---- packed f32x2 helpers (Blackwell FFMA2 path) ----
#define MUL2(out, a, b)    asm("mul.rn.f32x2 %0, %1, %2;"     : "=l"(out) : "l"(a), "l"(b))
#define ADD2(out, a, b)    asm("add.rn.f32x2 %0, %1, %2;"     : "=l"(out) : "l"(a), "l"(b))
#define FMA2(out, a, b, c) asm("fma.rn.f32x2 %0, %1, %2, %3;" : "=l"(out) : "l"(a), "l"(b), "l"(c))
#define PACK2(out, lo, hi) asm("mov.b64 %0, {%1, %2};" : "=l"(out) : "f"(lo), "f"(hi))
#define UNPK2(lo, hi, in)  asm("mov.b64 {%0, %1}, %2;" : "=f"(lo), "=f"(hi) : "l"(in))

__device__ __forceinline__ float tanh_approx(float x) {
    float r; asm("tanh.approx.f32 %0, %1;" : "=f"(r) : "f"(x)); return r;
}
__device__ __forceinline__ float lg2_approx(float x) {
    float r; asm("lg2.approx.f32 %0, %1;" : "=f"(r) : "f"(x)); return r;
}

// gather t-bit (1.0f vs 0.0f) of 8 target words into bits 0..7
__device__ __forceinline__ unsigned pack8(uint4 c0, uint4 c1) {
    unsigned a = __byte_perm(__byte_perm(c0.x, c0.y, 0x0073),
                             __byte_perm(c0.z, c0.w, 0x0073), 0x5410);
    unsigned b = __byte_perm(__byte_perm(c1.x, c1.y, 0x0073),
                             __byte_perm(c1.z, c1.w, 0x0073), 0x5410);
    unsigned ba = ((a & 0x01010101u) * 0x01020408u) >> 24;
    unsigned bb = ((b & 0x01010101u) * 0x01020408u) >> 24;
    return ba | (bb << 4);
}

// 12-bit window for row gy, cols x0-2 .. x0+9 (bit k <-> col x0-2+k). OOB bits 0.
__device__ __forceinline__ unsigned win_load8(const float* __restrict__ tb, int gy, int x0) {
    unsigned w = 0u;
    if ((unsigned)gy < (unsigned)HH) {
        const float* row = tb + gy * WW;
        uint4 c0 = *reinterpret_cast<const uint4*>(row + x0);
        uint4 c1 = *reinterpret_cast<const uint4*>(row + x0 + 4);
        w = pack8(c0, c1) << 2;
        if (x0 > 0) {
            uint2 l = *reinterpret_cast<const uint2*>(row + x0 - 2);
            w |= ((l.x >> 29) & 1u) | (((l.y >> 29) & 1u) << 1);
        }
        if (x0 + 8 < WW) {
            uint2 r = *reinterpret_cast<const uint2*>(row + x0 + 8);
            w |= (((r.x >> 29) & 1u) << 10) | (((r.y >> 29) & 1u) << 11);
        }
    }
    return w;
}

__device__ __forceinline__ unsigned or5(unsigned x)  { unsigned y = x | (x >> 1); unsigned z = y | (y >> 2); return z | (x >> 4); }
__device__ __forceinline__ unsigned or3(unsigned x)  { return x | (x >> 1) | (x >> 2); }
__device__ __forceinline__ unsigned and5(unsigned x) { unsigned y = x & (x >> 1); unsigned z = y & (y >> 2); return z & (x >> 4); }
__device__ __forceinline__ unsigned and3(unsigned x) { return x & (x >> 1) & (x >> 2); }

__global__ void __launch_bounds__(256) combined_loss_kernel(
    const float* __restrict__ inp,
    const float* __restrict__ tgt,
    float* __restrict__ out,
    float invN)
{
    const int b   = blockIdx.x;
    const int img = b >> 4;                     // 16 blocks/image, 32 rows each
    const int blk = b & 15;
    const int tid = threadIdx.x;
    const int strip = (blk << 2) | (tid >> 6);  // 0..63 strips of 8 rows
    const int x0    = (tid & 63) << 3;          // 8-px column group
    const int y0    = strip * RSTRIP;

    const float* tb = tgt + (size_t)img * HWSZ;
    const float* ib = inp + (size_t)img * HWSZ;

    unsigned wm2 = win_load8(tb, y0 - 2, x0);
    unsigned wm1 = win_load8(tb, y0 - 1, x0);
    unsigned w0  = win_load8(tb, y0,     x0);
    unsigned wp1 = win_load8(tb, y0 + 1, x0);

    uint64_t HALF2, FIVE2, C35_2, Q2, TQ2, NEG1_2;
    PACK2(HALF2, 0.5f, 0.5f);
    PACK2(FIVE2, 5.0f, 5.0f);
    PACK2(C35_2, 3.5f, 3.5f);
    PACK2(Q2,   0.25f, 0.25f);
    PACK2(TQ2,  0.75f, 0.75f);
    PACK2(NEG1_2, -1.0f, -1.0f);

    uint64_t aU2 = 0, aW2 = 0, aF2 = 0, aBW2 = 0;   // packed (0.0f,0.0f)
    int aT = 0;

    #pragma unroll 2
    for (int r = 0; r < RSTRIP; r++) {
        const int gy = y0 + r;
        const unsigned wp2 = win_load8(tb, gy + 2, x0);
        const float* irow = ib + gy * WW;

        // bit-parallel morphology: bit j valid for pixels j=0..7
        const unsigned anyb = or5(w0) | (or3(wm1) >> 1) | (or3(wp1) >> 1) | (wm2 >> 2) | (wp2 >> 2);
        const unsigned allb = and5(w0) & (and3(wm1) >> 1) & (and3(wp1) >> 1) & (wm2 >> 2) & (wp2 >> 2);
        const unsigned bnd   = anyb & ~allb;
        const unsigned tbits = (w0 >> 2) & 0xFFu;

        aT += __popc(tbits);
        const unsigned nt = ~tbits;
        const unsigned nb = ~bnd;

        // two 16B chunks, pairs processed right after each load
        #pragma unroll
        for (int c = 0; c < 2; c++) {
            const ulonglong2 q = *reinterpret_cast<const ulonglong2*>(irow + 4 * (2 * c));
            #pragma unroll
            for (int h = 0; h < 2; h++) {
                const uint64_t xpair = h ? q.y : q.x;
                const int j = 4 * c + 2 * h;

                const unsigned s0 = ((nt << (31 - j)) & 0x80000000u) | 0x3F000000u;
                const unsigned s1 = ((nt << (30 - j)) & 0x80000000u) | 0x3F000000u;
                const unsigned b0 = ((nb << (31 - j)) & 0x80000000u) | 0x3F000000u;
                const unsigned b1 = ((nb << (30 - j)) & 0x80000000u) | 0x3F000000u;
                uint64_t sgt2, sgb2;
                PACK2(sgt2, __uint_as_float(s0), __uint_as_float(s1));
                PACK2(sgb2, __uint_as_float(b0), __uint_as_float(b1));

                uint64_t harg; MUL2(harg, xpair, HALF2);
                float h0, h1; UNPK2(h0, h1, harg);
                uint64_t th2; PACK2(th2, tanh_approx(h0), tanh_approx(h1));

                uint64_t pt2; FMA2(pt2, sgt2, th2, HALF2);      // prob of true class
                float p0, p1; UNPK2(p0, p1, pt2);
                uint64_t lp2; PACK2(lp2, lg2_approx(p0), lg2_approx(p1)); // bce = -ln2*lp

                // ompt^2 = (1-pt)^2 = 0.75 + 0.25*th^2 - pt
                uint64_t thsq; MUL2(thsq, th2, th2);
                uint64_t s;    FMA2(s, thsq, Q2, TQ2);
                uint64_t osq;  FMA2(osq, pt2, NEG1_2, s);

                ADD2(aU2, aU2, pt2);
                FMA2(aW2, sgt2, pt2, aW2);
                FMA2(aF2, osq, lp2, aF2);
                uint64_t wgt; FMA2(wgt, FIVE2, sgb2, C35_2);    // {1,6}
                FMA2(aBW2, wgt, lp2, aBW2);
            }
        }

        wm2 = wm1; wm1 = w0; w0 = wp1; wp1 = wp2;
    }

    // horizontal fold of packed accumulators
    float u0,u1,w0f,w1f,f0,f1,bw0,bw1;
    UNPK2(u0,u1,aU2); UNPK2(w0f,w1f,aW2); UNPK2(f0,f1,aF2); UNPK2(bw0,bw1,aBW2);

    float v[5] = { f0+f1, w0f+w1f, u0+u1, (float)aT, bw0+bw1 };
    #pragma unroll
    for (int q = 0; q < 5; q++) {
        #pragma unroll
        for (int off = 16; off > 0; off >>= 1)
            v[q] += __shfl_down_sync(0xFFFFFFFFu, v[q], off);
    }

    __shared__ float sred[8][5];
    const int wid  = tid >> 5;
    const int lane = tid & 31;
    if (lane == 0) {
        #pragma unroll
        for (int q = 0; q < 5; q++) sred[wid][q] = v[q];
    }
    __syncthreads();

    __shared__ bool isLast;
    if (tid == 0) {
        #pragma unroll
        for (int q = 0; q < 5; q++) {
            float acc = sred[0][q];
            #pragma unroll
            for (int w = 1; w < 8; w++) acc += sred[w][q];
            g_part[q * MAXBLK + b] = acc;
        }
        __threadfence();
        isLast = (atomicAdd(&g_cnt, 1u) == gridDim.x - 1);
    }
    __syncthreads();

    if (isLast) {
        __threadfence();
        const int nb2 = gridDim.x;
        double d[5] = { 0, 0, 0, 0, 0 };
        for (int i = tid; i < nb2; i += 256) {
            #pragma unroll
            for (int q = 0; q < 5; q++) d[q] += (double)g_part[q * MAXBLK + i];
        }
        #pragma unroll
        for (int q = 0; q < 5; q++) {
            #pragma unroll
            for (int off = 16; off > 0; off >>= 1)
                d[q] += __shfl_down_sync(0xFFFFFFFFu, d[q], off);
        }
        __shared__ double dred[8][5];
        if (lane == 0) {
            #pragma unroll
            for (int q = 0; q < 5; q++) dred[wid][q] = d[q];
        }
        __syncthreads();
        if (tid == 0) {
            double t[5];
            #pragma unroll
            for (int q = 0; q < 5; q++) {
                double acc = dred[0][q];
                #pragma unroll
                for (int w = 1; w < 8; w++) acc += dred[w][q];
                t[q] = acc;
            }
            const double LN2 = 0.693147180559945309;
            const double N  = 1.0 / (double)invN;
            const double T  = t[3];
            const double V  = t[1] + 0.5 * t[2];        // sum(p*t)
            const double sumP = 2.0 * t[1] + (N - T);   // sum(p)
            const double focal = 0.25 * (-LN2 * t[0]) / N;
            const double dice  = (2.0 * V + 1e-6) / (sumP + T + 1e-6);
            const double bl    = (-LN2) * t[4] / N;     // sum(bce*w), w folded in-kernel
            out[0] = (float)(0.3 * focal + 0.4 * (1.0 - dice) + 0.3 * bl);
            g_cnt = 0;
        }
    }
}

extern "C" void kernel_launch(void* const* d_in, const int* in_sizes, int n_in,
                              void* d_out, int out_size) {
    const float* inp = (const float*)d_in[0];
    const float* tgt = (const float*)d_in[1];
    const int N = in_sizes[0];
    const int nimg = N / HWSZ;
    const int nblocks = nimg * 16;   // 16 blocks (32 rows) per image

    combined_loss_kernel<<<nblocks, 256>>>(inp, tgt, (float*)d_out, 1.0f / (float)N);
}

// round 14
// speedup vs baseline: 1.5511x; 1.0659x over previous
#include <cuda_runtime.h>
#include <cstdint>

#define HH 512
#define WW 512
#define HWSZ (HH * WW)
#define RSTRIP 8
#define MAXBLK 2048

__device__ float g_part[5 * MAXBLK];
__device__ unsigned g_cnt;   // zero-init; last block resets each launch

// ---- packed f32x2 helpers (Blackwell FFMA2 path) ----
#define MUL2(out, a, b)    asm("mul.rn.f32x2 %0, %1, %2;"     : "=l"(out) : "l"(a), "l"(b))
#define ADD2(out, a, b)    asm("add.rn.f32x2 %0, %1, %2;"     : "=l"(out) : "l"(a), "l"(b))
#define FMA2(out, a, b, c) asm("fma.rn.f32x2 %0, %1, %2, %3;" : "=l"(out) : "l"(a), "l"(b), "l"(c))
#define PACK2(out, lo, hi) asm("mov.b64 %0, {%1, %2};" : "=l"(out) : "f"(lo), "f"(hi))
#define UNPK2(lo, hi, in)  asm("mov.b64 {%0, %1}, %2;" : "=f"(lo), "=f"(hi) : "l"(in))

__device__ __forceinline__ float tanh_approx(float x) {
    float r; asm("tanh.approx.f32 %0, %1;" : "=f"(r) : "f"(x)); return r;
}
__device__ __forceinline__ float lg2_approx(float x) {
    float r; asm("lg2.approx.f32 %0, %1;" : "=f"(r) : "f"(x)); return r;
}

// gather t-bit (1.0f vs 0.0f) of 8 target words into bits 0..7
__device__ __forceinline__ unsigned pack8(uint4 c0, uint4 c1) {
    unsigned a = __byte_perm(__byte_perm(c0.x, c0.y, 0x0073),
                             __byte_perm(c0.z, c0.w, 0x0073), 0x5410);
    unsigned b = __byte_perm(__byte_perm(c1.x, c1.y, 0x0073),
                             __byte_perm(c1.z, c1.w, 0x0073), 0x5410);
    unsigned ba = ((a & 0x01010101u) * 0x01020408u) >> 24;
    unsigned bb = ((b & 0x01010101u) * 0x01020408u) >> 24;
    return ba | (bb << 4);
}

// 12-bit window for row gy, cols x0-2 .. x0+9 (bit k <-> col x0-2+k). OOB bits 0.
__device__ __forceinline__ unsigned win_load8(const float* __restrict__ tb, int gy, int x0) {
    unsigned w = 0u;
    if ((unsigned)gy < (unsigned)HH) {
        const float* row = tb + gy * WW;
        uint4 c0 = *reinterpret_cast<const uint4*>(row + x0);
        uint4 c1 = *reinterpret_cast<const uint4*>(row + x0 + 4);
        w = pack8(c0, c1) << 2;
        if (x0 > 0) {
            uint2 l = *reinterpret_cast<const uint2*>(row + x0 - 2);
            w |= ((l.x >> 29) & 1u) | (((l.y >> 29) & 1u) << 1);
        }
        if (x0 + 8 < WW) {
            uint2 r = *reinterpret_cast<const uint2*>(row + x0 + 8);
            w |= (((r.x >> 29) & 1u) << 10) | (((r.y >> 29) & 1u) << 11);
        }
    }
    return w;
}

__device__ __forceinline__ unsigned or5(unsigned x)  { unsigned y = x | (x >> 1); unsigned z = y | (y >> 2); return z | (x >> 4); }
__device__ __forceinline__ unsigned or3(unsigned x)  { return x | (x >> 1) | (x >> 2); }
__device__ __forceinline__ unsigned and5(unsigned x) { unsigned y = x & (x >> 1); unsigned z = y & (y >> 2); return z & (x >> 4); }
__device__ __forceinline__ unsigned and3(unsigned x) { return x & (x >> 1) & (x >> 2); }

__global__ void __launch_bounds__(256) combined_loss_kernel(
    const float* __restrict__ inp,
    const float* __restrict__ tgt,
    float* __restrict__ out,
    float invN)
{
    const int b   = blockIdx.x;
    const int img = b >> 4;                     // 16 blocks/image, 32 rows each
    const int blk = b & 15;
    const int tid = threadIdx.x;
    const int strip = (blk << 2) | (tid >> 6);  // 0..63 strips of 8 rows
    const int x0    = (tid & 63) << 3;          // 8-px column group
    const int y0    = strip * RSTRIP;

    const float* tb = tgt + (size_t)img * HWSZ;
    const float* ib = inp + (size_t)img * HWSZ;

    unsigned wm2 = win_load8(tb, y0 - 2, x0);
    unsigned wm1 = win_load8(tb, y0 - 1, x0);
    unsigned w0  = win_load8(tb, y0,     x0);
    unsigned wp1 = win_load8(tb, y0 + 1, x0);

    uint64_t HALF2, NEGHALF2;
    PACK2(HALF2,    0.5f,  0.5f);
    PACK2(NEGHALF2, -0.5f, -0.5f);

    // accumulators: A=sum th, U=sum pt, F=sum ompt^2*lg2(pt), BW=sum wgt*lg2(pt)
    uint64_t aA2 = 0, aU2 = 0, aF2 = 0, aBW2 = 0;
    int aT = 0;

    #pragma unroll 2
    for (int r = 0; r < RSTRIP; r++) {
        const int gy = y0 + r;
        const unsigned wp2 = win_load8(tb, gy + 2, x0);
        const float* irow = ib + gy * WW;

        // bit-parallel morphology: bit j valid for pixels j=0..7
        const unsigned anyb = or5(w0) | (or3(wm1) >> 1) | (or3(wp1) >> 1) | (wm2 >> 2) | (wp2 >> 2);
        const unsigned allb = and5(w0) & (and3(wm1) >> 1) & (and3(wp1) >> 1) & (wm2 >> 2) & (wp2 >> 2);
        const unsigned bnd   = anyb & ~allb;
        const unsigned tbits = (w0 >> 2) & 0xFFu;

        aT += __popc(tbits);
        const unsigned nt = ~tbits;

        // two 16B chunks, pairs processed right after each load
        #pragma unroll
        for (int c = 0; c < 2; c++) {
            const ulonglong2 q = *reinterpret_cast<const ulonglong2*>(irow + 8 * c);
            #pragma unroll
            for (int h = 0; h < 2; h++) {
                const uint64_t xpair = h ? q.y : q.x;
                const int j = 4 * c + 2 * h;

                uint64_t harg; MUL2(harg, xpair, HALF2);
                float h0, h1; UNPK2(h0, h1, harg);
                const float t0 = tanh_approx(h0);
                const float t1 = tanh_approx(h1);
                uint64_t th2; PACK2(th2, t0, t1);
                ADD2(aA2, aA2, th2);

                // signed tanh: flip sign when t==0 (bit from nt)
                const unsigned sb0 = (nt << (31 - j)) & 0x80000000u;
                const unsigned sb1 = (nt << (30 - j)) & 0x80000000u;
                const float ts0 = __uint_as_float(__float_as_uint(t0) ^ sb0);
                const float ts1 = __uint_as_float(__float_as_uint(t1) ^ sb1);
                uint64_t ths2; PACK2(ths2, ts0, ts1);

                uint64_t pt2;  FMA2(pt2,  ths2, HALF2,    HALF2);   // pt  = 0.5 + 0.5*th_s (exact)
                uint64_t om2;  FMA2(om2,  ths2, NEGHALF2, HALF2);   // 1-pt = 0.5 - 0.5*th_s (exact)
                ADD2(aU2, aU2, pt2);

                float p0, p1; UNPK2(p0, p1, pt2);
                uint64_t lp2; PACK2(lp2, lg2_approx(p0), lg2_approx(p1)); // bce = -ln2*lp

                uint64_t osq; MUL2(osq, om2, om2);
                FMA2(aF2, osq, lp2, aF2);

                // wgt in {1.0f, 6.0f} from boundary bit via integer add
                const unsigned m0 = (bnd >> j) & 1u;
                const unsigned m1 = (bnd >> (j + 1)) & 1u;
                uint64_t wgt2;
                PACK2(wgt2, __uint_as_float(0x3F800000u + m0 * 0x01400000u),
                            __uint_as_float(0x3F800000u + m1 * 0x01400000u));
                FMA2(aBW2, wgt2, lp2, aBW2);
            }
        }

        wm2 = wm1; wm1 = w0; w0 = wp1; wp1 = wp2;
    }

    // horizontal fold of packed accumulators
    float a0,a1,u0,u1,f0,f1,bw0,bw1;
    UNPK2(a0,a1,aA2); UNPK2(u0,u1,aU2); UNPK2(f0,f1,aF2); UNPK2(bw0,bw1,aBW2);

    float v[5] = { f0+f1, a0+a1, u0+u1, (float)aT, bw0+bw1 };
    #pragma unroll
    for (int q = 0; q < 5; q++) {
        #pragma unroll
        for (int off = 16; off > 0; off >>= 1)
            v[q] += __shfl_down_sync(0xFFFFFFFFu, v[q], off);
    }

    __shared__ float sred[8][5];
    const int wid  = tid >> 5;
    const int lane = tid & 31;
    if (lane == 0) {
        #pragma unroll
        for (int q = 0; q < 5; q++) sred[wid][q] = v[q];
    }
    __syncthreads();

    __shared__ bool isLast;
    if (tid == 0) {
        #pragma unroll
        for (int q = 0; q < 5; q++) {
            float acc = sred[0][q];
            #pragma unroll
            for (int w = 1; w < 8; w++) acc += sred[w][q];
            g_part[q * MAXBLK + b] = acc;
        }
        __threadfence();
        isLast = (atomicAdd(&g_cnt, 1u) == gridDim.x - 1);
    }
    __syncthreads();

    if (isLast) {
        __threadfence();
        const int nb2 = gridDim.x;
        double d[5] = { 0, 0, 0, 0, 0 };
        for (int i = tid; i < nb2; i += 256) {
            #pragma unroll
            for (int q = 0; q < 5; q++) d[q] += (double)g_part[q * MAXBLK + i];
        }
        #pragma unroll
        for (int q = 0; q < 5; q++) {
            #pragma unroll
            for (int off = 16; off > 0; off >>= 1)
                d[q] += __shfl_down_sync(0xFFFFFFFFu, d[q], off);
        }
        __shared__ double dred[8][5];
        if (lane == 0) {
            #pragma unroll
            for (int q = 0; q < 5; q++) dred[wid][q] = d[q];
        }
        __syncthreads();
        if (tid == 0) {
            double t[5];
            #pragma unroll
            for (int q = 0; q < 5; q++) {
                double acc = dred[0][q];
                #pragma unroll
                for (int w = 1; w < 8; w++) acc += dred[w][q];
                t[q] = acc;
            }
            const double LN2 = 0.693147180559945309;
            const double N  = 1.0 / (double)invN;
            const double F  = t[0], A = t[1], U = t[2], T = t[3], BW = t[4];
            const double sumP  = 0.5 * N + 0.5 * A;                    // sum sigmoid
            const double sumPT = 0.5 * T + 0.25 * A + 0.5 * U - 0.25 * N;  // sum p*t
            const double focal = 0.25 * (-LN2 * F) / N;
            const double dice  = (2.0 * sumPT + 1e-6) / (sumP + T + 1e-6);
            const double bl    = (-LN2) * BW / N;
            out[0] = (float)(0.3 * focal + 0.4 * (1.0 - dice) + 0.3 * bl);
            g_cnt = 0;
        }
    }
}

extern "C" void kernel_launch(void* const* d_in, const int* in_sizes, int n_in,
                              void* d_out, int out_size) {
    const float* inp = (const float*)d_in[0];
    const float* tgt = (const float*)d_in[1];
    const int N = in_sizes[0];
    const int nimg = N / HWSZ;
    const int nblocks = nimg * 16;   // 16 blocks (32 rows) per image

    combined_loss_kernel<<<nblocks, 256>>>(inp, tgt, (float*)d_out, 1.0f / (float)N);
}